// round 15
// baseline (speedup 1.0000x reference)
#include <cuda_runtime.h>
#include <math.h>
#include <stdint.h>

#define BB 4
#define SS 1024
#define DD 1024
#define HH 16
#define DKK 64

// Scratch (no allocations allowed).
__device__ float g_q[BB * HH * SS * DKK];
__device__ float g_k[BB * HH * SS * DKK];
__device__ float g_v[BB * HH * SS * DKK];
__device__ float g_x[BB * SS * DD];
__device__ uint32_t g_mbits[BB * SS * (SS / 32)];

__device__ __forceinline__ uint32_t f2tf32(float x) {
    uint32_t r;
    asm("cvt.rna.tf32.f32 %0, %1;" : "=r"(r) : "f"(x));
    return r;
}

__device__ __forceinline__ void mma_tf32(float& c0, float& c1, float& c2, float& c3,
                                         uint32_t a0, uint32_t a1, uint32_t a2, uint32_t a3,
                                         uint32_t b0, uint32_t b1) {
    asm volatile(
        "mma.sync.aligned.m16n8k8.row.col.f32.tf32.tf32.f32 "
        "{%0,%1,%2,%3}, {%4,%5,%6,%7}, {%8,%9}, {%0,%1,%2,%3};"
        : "+f"(c0), "+f"(c1), "+f"(c2), "+f"(c3)
        : "r"(a0), "r"(a1), "r"(a2), "r"(a3), "r"(b0), "r"(b1));
}

// ---------------------------------------------------------------------------
// NT tensor-core GEMM (tf32) — R14-proven (623.0 us wall). GPAD=18 (2 mod 4:
// staging-store banks span 16, 2-way conflicts; LDS.64 stays 8B-aligned).
// BM=BN=128, BK=16, 128 thr = 4 warps (2m x 2n), warp tile 64x64.
// QKV==1: fused QKV via blockIdx.z; QKV==0: out-proj, A = g_x (device bind).
// ---------------------------------------------------------------------------
#define GPAD 18

template <int QKV>
__global__ __launch_bounds__(128) void gemm_tc(const float* __restrict__ A0,
                                               const float* __restrict__ A1,
                                               const float* __restrict__ A2,
                                               const float* __restrict__ W0,
                                               const float* __restrict__ W1,
                                               const float* __restrict__ W2,
                                               const float* __restrict__ B0,
                                               const float* __restrict__ B1,
                                               const float* __restrict__ B2,
                                               float* __restrict__ C) {
    __shared__ uint32_t As[2][128 * GPAD];
    __shared__ uint32_t Bs[2][128 * GPAD];

    const int tid  = threadIdx.x;
    const int lane = tid & 31;
    const int warp = tid >> 5;       // 0..3
    const int wm   = warp >> 1;      // 0..1
    const int wn   = warp & 1;       // 0..1
    const int g    = lane >> 2;      // 0..7
    const int t    = lane & 3;       // 0..3
    const int m0 = blockIdx.y * 128;
    const int n0 = blockIdx.x * 128;
    const int z  = QKV ? blockIdx.z : 0;

    const float* A = QKV ? (z == 0 ? A0 : z == 1 ? A1 : A2) : g_x;  // device-side bind
    const float* W = QKV ? (z == 0 ? W0 : z == 1 ? W1 : W2) : W0;
    const float* bias = QKV ? (z == 0 ? B0 : z == 1 ? B1 : B2) : B0;

    // Staging: 2 half-rows per array per thread (256 half-rows / 128 thr).
    const int row0 = tid >> 1;            // 0..63
    const int kh0  = (tid & 1) * 8;
    const int row1 = row0 + 64;           // 64..127
    const float* Ap0 = A + (size_t)(m0 + row0) * DD + kh0;
    const float* Ap1 = A + (size_t)(m0 + row1) * DD + kh0;
    const float* Wp0 = W + (size_t)(n0 + row0) * DD + kh0;
    const float* Wp1 = W + (size_t)(n0 + row1) * DD + kh0;
    const int sb0 = row0 * GPAD + kh0;
    const int sb1 = row1 * GPAD + kh0;

    float acc[4][8][4];
#pragma unroll
    for (int i = 0; i < 4; i++)
#pragma unroll
        for (int j = 0; j < 8; j++)
#pragma unroll
            for (int c = 0; c < 4; c++) acc[i][j][c] = 0.f;

    // Prefetch registers: 2 half-rows x 2 float4, per array.
    float4 rA0a, rA0b, rA1a, rA1b, rB0a, rB0b, rB1a, rB1b;
    rA0a = *(const float4*)(Ap0);     rA0b = *(const float4*)(Ap0 + 4);
    rA1a = *(const float4*)(Ap1);     rA1b = *(const float4*)(Ap1 + 4);
    rB0a = *(const float4*)(Wp0);     rB0b = *(const float4*)(Wp0 + 4);
    rB1a = *(const float4*)(Wp1);     rB1b = *(const float4*)(Wp1 + 4);

    // Scalar pair-interleaved half-row store: pos 0..7 = k0,k4,k1,k5,k2,k6,k3,k7.
    auto sts_half = [&](uint32_t* S, int sb, float4 lo, float4 hi) {
        S[sb + 0] = f2tf32(lo.x); S[sb + 2] = f2tf32(lo.y);
        S[sb + 4] = f2tf32(lo.z); S[sb + 6] = f2tf32(lo.w);
        S[sb + 1] = f2tf32(hi.x); S[sb + 3] = f2tf32(hi.y);
        S[sb + 5] = f2tf32(hi.z); S[sb + 7] = f2tf32(hi.w);
    };

    auto sts_tile = [&](uint32_t* SA, uint32_t* SB) {
        sts_half(SA, sb0, rA0a, rA0b);
        sts_half(SA, sb1, rA1a, rA1b);
        sts_half(SB, sb0, rB0a, rB0b);
        sts_half(SB, sb1, rB1a, rB1b);
    };

    sts_tile(As[0], Bs[0]);
    __syncthreads();

    int cur = 0;
    const int NTILES = DD / 16;
    for (int it = 0; it < NTILES; ++it) {
        if (it + 1 < NTILES) {
            const int ko = (it + 1) * 16;
            rA0a = *(const float4*)(Ap0 + ko);  rA0b = *(const float4*)(Ap0 + ko + 4);
            rA1a = *(const float4*)(Ap1 + ko);  rA1b = *(const float4*)(Ap1 + ko + 4);
            rB0a = *(const float4*)(Wp0 + ko);  rB0b = *(const float4*)(Wp0 + ko + 4);
            rB1a = *(const float4*)(Wp1 + ko);  rB1b = *(const float4*)(Wp1 + ko + 4);
        }

        const uint32_t* SA = As[cur];
        const uint32_t* SB = Bs[cur];
#pragma unroll
        for (int s = 0; s < 2; s++) {
            uint32_t a[4][4];
#pragma unroll
            for (int mi = 0; mi < 4; mi++) {
                const int r0 = wm * 64 + mi * 16 + g;
                uint2 p0 = *(const uint2*)&SA[r0 * GPAD + s * 8 + 2 * t];
                uint2 p1 = *(const uint2*)&SA[(r0 + 8) * GPAD + s * 8 + 2 * t];
                a[mi][0] = p0.x; a[mi][1] = p1.x; a[mi][2] = p0.y; a[mi][3] = p1.y;
            }
            uint32_t b[8][2];
#pragma unroll
            for (int nj = 0; nj < 8; nj++) {
                uint2 q = *(const uint2*)&SB[(wn * 64 + nj * 8 + g) * GPAD + s * 8 + 2 * t];
                b[nj][0] = q.x; b[nj][1] = q.y;
            }
#pragma unroll
            for (int mi = 0; mi < 4; mi++)
#pragma unroll
                for (int nj = 0; nj < 8; nj++)
                    mma_tf32(acc[mi][nj][0], acc[mi][nj][1], acc[mi][nj][2], acc[mi][nj][3],
                             a[mi][0], a[mi][1], a[mi][2], a[mi][3],
                             b[nj][0], b[nj][1]);
        }

        if (it + 1 < NTILES) {
            sts_tile(As[cur ^ 1], Bs[cur ^ 1]);
            __syncthreads();
            cur ^= 1;
        }
    }

#pragma unroll
    for (int mi = 0; mi < 4; mi++) {
#pragma unroll
        for (int nj = 0; nj < 8; nj++) {
            const int n = n0 + wn * 64 + nj * 8 + 2 * t;
            const float bn0 = __ldg(&bias[n]);
            const float bn1 = __ldg(&bias[n + 1]);
#pragma unroll
            for (int rr = 0; rr < 2; rr++) {
                const int m = m0 + wm * 64 + mi * 16 + g + rr * 8;
                const float v0 = acc[mi][nj][rr * 2 + 0] + bn0;
                const float v1 = acc[mi][nj][rr * 2 + 1] + bn1;
                if (!QKV) {
                    *(float2*)&C[(size_t)m * DD + n] = make_float2(v0, v1);
                } else {
                    const int bb = m >> 10;
                    const int s  = m & (SS - 1);
                    const int h  = n >> 6;
                    const int dk = n & (DKK - 1);
                    float* dst = (z == 0) ? g_q : (z == 1) ? g_k : g_v;
                    *(float2*)&dst[(((size_t)(bb * HH + h)) * SS + s) * DKK + dk] =
                        make_float2(v0, v1);
                }
            }
        }
    }
}

// ---------------------------------------------------------------------------
// Mask bit-pack: one warp packs 32 ints -> 1 uint32 via ballot.
// ---------------------------------------------------------------------------
__global__ __launch_bounds__(256) void pack_mask(const int* __restrict__ mask) {
    const int gid = blockIdx.x * 256 + threadIdx.x;
    const int v = mask[gid] != 0;
    const uint32_t bits = __ballot_sync(0xffffffffu, v);
    if ((threadIdx.x & 31) == 0) g_mbits[gid >> 5] = bits;
}

// ---------------------------------------------------------------------------
// Tensor-core flash attention — R6/R9-proven structure, single change:
// ATP 72 -> 74 (gcd(74,32)=2 vs gcd(72,32)=8: tile-loader store banks span
// 16 instead of 4 groups -> conflicts halve; all uint2 accesses stay at even
// word offsets = 8B-aligned). Grid (S/64, B*H), 128 thr = 4 warps.
// ---------------------------------------------------------------------------
#define ATP 74

__global__ __launch_bounds__(128) void attn_tc() {
    extern __shared__ uint32_t smu[];
    uint32_t* Qs = smu;              // [64 q][ATP] d-interleaved
    uint32_t* Ks = Qs + 64 * ATP;    // [64 kk][ATP] d-interleaved
    uint32_t* Vs = Ks + 64 * ATP;    // [64 kk][ATP] d-interleaved
    uint32_t* Ps = Vs + 64 * ATP;    // [64 q][ATP] kk-interleaved

    const int tid  = threadIdx.x;
    const int lane = tid & 31;
    const int warp = tid >> 5;
    const int g = lane >> 2;
    const int t = lane & 3;
    const int bh = blockIdx.y;
    const int b = bh >> 4, h = bh & 15;
    const int q0 = blockIdx.x * 64;

    const float* qg = g_q + ((size_t)bh * SS + q0) * DKK;
    const float* kg = g_k + (size_t)bh * SS * DKK;
    const float* vg = g_v + (size_t)bh * SS * DKK;

#pragma unroll
    for (int u = 0; u < 8; u++) {
        const int off = tid + u * 128;
        float4 qv = *(const float4*)(qg + (size_t)off * 4);
        const int row = off >> 4;
        const int d0  = (off & 15) * 4;
        const int base = row * ATP + (d0 >> 3) * 8 + ((d0 & 7) ? 1 : 0);
        Qs[base + 0] = f2tf32(qv.x); Qs[base + 2] = f2tf32(qv.y);
        Qs[base + 4] = f2tf32(qv.z); Qs[base + 6] = f2tf32(qv.w);
    }
    __syncthreads();

    uint32_t aq[8][4];
#pragma unroll
    for (int ks = 0; ks < 8; ks++) {
        uint2 p0 = *(const uint2*)&Qs[(warp * 16 + g) * ATP + ks * 8 + 2 * t];
        uint2 p1 = *(const uint2*)&Qs[(warp * 16 + g + 8) * ATP + ks * 8 + 2 * t];
        aq[ks][0] = p0.x; aq[ks][1] = p1.x; aq[ks][2] = p0.y; aq[ks][3] = p1.y;
    }

    float o[8][4];
#pragma unroll
    for (int nj = 0; nj < 8; nj++)
#pragma unroll
        for (int c = 0; c < 4; c++) o[nj][c] = 0.f;
    float m0 = -1e30f, m1 = -1e30f, l0 = 0.f, l1 = 0.f;

    const uint32_t* mrow = g_mbits + ((size_t)b * SS + (q0 + warp * 16 + g)) * (SS / 32);
    const int ig = 2 * (g & 3) + (g >> 2);

    for (int kt = 0; kt < 16; kt++) {
        __syncthreads();
#pragma unroll
        for (int u = 0; u < 8; u++) {
            const int off = tid + u * 128;
            const int row = off >> 4;
            const int d0  = (off & 15) * 4;
            const int base = row * ATP + (d0 >> 3) * 8 + ((d0 & 7) ? 1 : 0);
            float4 kv = *(const float4*)(kg + (size_t)kt * 4096 + (size_t)off * 4);
            Ks[base + 0] = f2tf32(kv.x); Ks[base + 2] = f2tf32(kv.y);
            Ks[base + 4] = f2tf32(kv.z); Ks[base + 6] = f2tf32(kv.w);
            float4 vv = *(const float4*)(vg + (size_t)kt * 4096 + (size_t)off * 4);
            Vs[base + 0] = f2tf32(vv.x); Vs[base + 2] = f2tf32(vv.y);
            Vs[base + 4] = f2tf32(vv.z); Vs[base + 6] = f2tf32(vv.w);
        }
        __syncthreads();

        // S = Q K^T  (16 x 64 per warp)
        float s[8][4];
#pragma unroll
        for (int nj = 0; nj < 8; nj++)
#pragma unroll
            for (int c = 0; c < 4; c++) s[nj][c] = 0.f;
#pragma unroll
        for (int nj = 0; nj < 8; nj++)
#pragma unroll
            for (int ks = 0; ks < 8; ks++) {
                uint2 kb = *(const uint2*)&Ks[(nj * 8 + g) * ATP + ks * 8 + 2 * t];
                mma_tf32(s[nj][0], s[nj][1], s[nj][2], s[nj][3],
                         aq[ks][0], aq[ks][1], aq[ks][2], aq[ks][3], kb.x, kb.y);
            }

        // Mask + scale (bit-packed).
        const uint32_t w0lo = mrow[kt * 2];
        const uint32_t w0hi = mrow[kt * 2 + 1];
        const uint32_t w1lo = mrow[8 * (SS / 32) + kt * 2];
        const uint32_t w1hi = mrow[8 * (SS / 32) + kt * 2 + 1];
#pragma unroll
        for (int nj = 0; nj < 8; nj++) {
            const uint32_t wr0 = (nj < 4) ? w0lo : w0hi;
            const uint32_t wr1 = (nj < 4) ? w1lo : w1hi;
            const int sh = (nj & 3) * 8 + 2 * t;
            s[nj][0] = ((wr0 >> sh) & 1u)       ? s[nj][0] * 0.125f : -1e9f;
            s[nj][1] = ((wr0 >> (sh + 1)) & 1u) ? s[nj][1] * 0.125f : -1e9f;
            s[nj][2] = ((wr1 >> sh) & 1u)       ? s[nj][2] * 0.125f : -1e9f;
            s[nj][3] = ((wr1 >> (sh + 1)) & 1u) ? s[nj][3] * 0.125f : -1e9f;
        }

        // Online softmax.
        float mx0 = -1e30f, mx1 = -1e30f;
#pragma unroll
        for (int nj = 0; nj < 8; nj++) {
            mx0 = fmaxf(mx0, fmaxf(s[nj][0], s[nj][1]));
            mx1 = fmaxf(mx1, fmaxf(s[nj][2], s[nj][3]));
        }
        mx0 = fmaxf(mx0, __shfl_xor_sync(0xffffffffu, mx0, 1));
        mx0 = fmaxf(mx0, __shfl_xor_sync(0xffffffffu, mx0, 2));
        mx1 = fmaxf(mx1, __shfl_xor_sync(0xffffffffu, mx1, 1));
        mx1 = fmaxf(mx1, __shfl_xor_sync(0xffffffffu, mx1, 2));
        const float mn0 = fmaxf(m0, mx0), mn1 = fmaxf(m1, mx1);
        const float cr0 = __expf(m0 - mn0), cr1 = __expf(m1 - mn1);
        m0 = mn0; m1 = mn1;

        const int pa = 2 * ((2 * t) & 3) + ((2 * t) >> 2);
        const int pb = 2 * ((2 * t + 1) & 3) + ((2 * t + 1) >> 2);
        float rs0 = 0.f, rs1 = 0.f;
#pragma unroll
        for (int nj = 0; nj < 8; nj++) {
            const float p0 = __uint_as_float(f2tf32(__expf(s[nj][0] - m0)));
            const float p1 = __uint_as_float(f2tf32(__expf(s[nj][1] - m0)));
            const float p2 = __uint_as_float(f2tf32(__expf(s[nj][2] - m1)));
            const float p3 = __uint_as_float(f2tf32(__expf(s[nj][3] - m1)));
            rs0 += p0 + p1;
            rs1 += p2 + p3;
            const int pb0 = (warp * 16 + g) * ATP + nj * 8;
            const int pb1 = (warp * 16 + g + 8) * ATP + nj * 8;
            Ps[pb0 + pa] = __float_as_uint(p0);
            Ps[pb0 + pb] = __float_as_uint(p1);
            Ps[pb1 + pa] = __float_as_uint(p2);
            Ps[pb1 + pb] = __float_as_uint(p3);
        }
        rs0 += __shfl_xor_sync(0xffffffffu, rs0, 1);
        rs0 += __shfl_xor_sync(0xffffffffu, rs0, 2);
        rs1 += __shfl_xor_sync(0xffffffffu, rs1, 1);
        rs1 += __shfl_xor_sync(0xffffffffu, rs1, 2);
        l0 = l0 * cr0 + rs0;
        l1 = l1 * cr1 + rs1;
#pragma unroll
        for (int nj = 0; nj < 8; nj++) {
            o[nj][0] *= cr0; o[nj][1] *= cr0;
            o[nj][2] *= cr1; o[nj][3] *= cr1;
        }
        __syncwarp();

        // O += P V
#pragma unroll
        for (int ks = 0; ks < 8; ks++) {
            uint2 p0 = *(const uint2*)&Ps[(warp * 16 + g) * ATP + ks * 8 + 2 * t];
            uint2 p1 = *(const uint2*)&Ps[(warp * 16 + g + 8) * ATP + ks * 8 + 2 * t];
#pragma unroll
            for (int nj = 0; nj < 8; nj++) {
                const uint32_t b0 = Vs[(ks * 8 + t) * ATP + nj * 8 + ig];
                const uint32_t b1 = Vs[(ks * 8 + t + 4) * ATP + nj * 8 + ig];
                mma_tf32(o[nj][0], o[nj][1], o[nj][2], o[nj][3],
                         p0.x, p1.x, p0.y, p1.y, b0, b1);
            }
        }
        __syncwarp();
    }

    // Epilogue.
    const float i0 = 1.f / l0, i1 = 1.f / l1;
    const size_t r0 = ((size_t)(b * SS + q0 + warp * 16 + g)) * DD + h * 64;
    const size_t r1 = r0 + (size_t)8 * DD;
#pragma unroll
    for (int nj = 0; nj < 8; nj++) {
        *(float2*)&g_x[r0 + nj * 8 + 2 * t] = make_float2(o[nj][0] * i0, o[nj][1] * i0);
        *(float2*)&g_x[r1 + nj * 8 + 2 * t] = make_float2(o[nj][2] * i1, o[nj][3] * i1);
    }
}

// ---------------------------------------------------------------------------
extern "C" void kernel_launch(void* const* d_in, const int* in_sizes, int n_in,
                              void* d_out, int out_size) {
    const float* query = (const float*)d_in[0];
    const float* key   = (const float*)d_in[1];
    const float* value = (const float*)d_in[2];
    const int*   mask  = (const int*)d_in[3];
    const float* wq = (const float*)d_in[4];
    const float* bq = (const float*)d_in[5];
    const float* wk = (const float*)d_in[6];
    const float* bk = (const float*)d_in[7];
    const float* wv = (const float*)d_in[8];
    const float* bv = (const float*)d_in[9];
    const float* wo = (const float*)d_in[10];
    const float* bo = (const float*)d_in[11];
    float* out = (float*)d_out;

    static int smem_ok = 0;
    const int attn_smem = 4 * 64 * ATP * (int)sizeof(uint32_t);  // 75776 B
    if (!smem_ok) {
        cudaFuncSetAttribute(attn_tc, cudaFuncAttributeMaxDynamicSharedMemorySize,
                             attn_smem);
        smem_ok = 1;
    }

    pack_mask<<<(BB * SS * SS) / 256, 256>>>(mask);

    dim3 gq(DD / 128, (BB * SS) / 128, 3);  // fused QKV
    gemm_tc<1><<<gq, 128>>>(query, key, value, wq, wk, wv, bq, bk, bv, nullptr);

    attn_tc<<<dim3(SS / 64, BB * HH), 128, attn_smem>>>();

    dim3 go(DD / 128, (BB * SS) / 128, 1);
    gemm_tc<0><<<go, 128>>>(nullptr, nullptr, nullptr, wo, nullptr, nullptr,
                            bo, nullptr, nullptr, out);
}

// round 16
// speedup vs baseline: 1.0338x; 1.0338x over previous
#include <cuda_runtime.h>
#include <math.h>
#include <stdint.h>

#define BB 4
#define SS 1024
#define DD 1024
#define HH 16
#define DKK 64

// Scratch (no allocations allowed).
__device__ float g_q[BB * HH * SS * DKK];
__device__ float g_k[BB * HH * SS * DKK];
__device__ float g_v[BB * HH * SS * DKK];
__device__ float g_x[BB * SS * DD];
__device__ uint32_t g_mbits[BB * SS * (SS / 32)];

__device__ __forceinline__ uint32_t f2tf32(float x) {
    uint32_t r;
    asm("cvt.rna.tf32.f32 %0, %1;" : "=r"(r) : "f"(x));
    return r;
}

__device__ __forceinline__ void mma_tf32(float& c0, float& c1, float& c2, float& c3,
                                         uint32_t a0, uint32_t a1, uint32_t a2, uint32_t a3,
                                         uint32_t b0, uint32_t b1) {
    asm volatile(
        "mma.sync.aligned.m16n8k8.row.col.f32.tf32.tf32.f32 "
        "{%0,%1,%2,%3}, {%4,%5,%6,%7}, {%8,%9}, {%0,%1,%2,%3};"
        : "+f"(c0), "+f"(c1), "+f"(c2), "+f"(c3)
        : "r"(a0), "r"(a1), "r"(a2), "r"(a3), "r"(b0), "r"(b1));
}

// ---------------------------------------------------------------------------
// NT tensor-core GEMM (tf32) — R14-proven (623.0 us wall). GPAD=18 (2 mod 4:
// staging-store banks span 16, 2-way conflicts; LDS.64 stays 8B-aligned).
// BM=BN=128, BK=16, 128 thr = 4 warps (2m x 2n), warp tile 64x64.
// QKV==1: fused QKV via blockIdx.z; QKV==0: out-proj, A = g_x (device bind).
// ---------------------------------------------------------------------------
#define GPAD 18

template <int QKV>
__global__ __launch_bounds__(128) void gemm_tc(const float* __restrict__ A0,
                                               const float* __restrict__ A1,
                                               const float* __restrict__ A2,
                                               const float* __restrict__ W0,
                                               const float* __restrict__ W1,
                                               const float* __restrict__ W2,
                                               const float* __restrict__ B0,
                                               const float* __restrict__ B1,
                                               const float* __restrict__ B2,
                                               float* __restrict__ C) {
    __shared__ uint32_t As[2][128 * GPAD];
    __shared__ uint32_t Bs[2][128 * GPAD];

    const int tid  = threadIdx.x;
    const int lane = tid & 31;
    const int warp = tid >> 5;       // 0..3
    const int wm   = warp >> 1;      // 0..1
    const int wn   = warp & 1;       // 0..1
    const int g    = lane >> 2;      // 0..7
    const int t    = lane & 3;       // 0..3
    const int m0 = blockIdx.y * 128;
    const int n0 = blockIdx.x * 128;
    const int z  = QKV ? blockIdx.z : 0;

    const float* A = QKV ? (z == 0 ? A0 : z == 1 ? A1 : A2) : g_x;  // device-side bind
    const float* W = QKV ? (z == 0 ? W0 : z == 1 ? W1 : W2) : W0;
    const float* bias = QKV ? (z == 0 ? B0 : z == 1 ? B1 : B2) : B0;

    // Staging: 2 half-rows per array per thread (256 half-rows / 128 thr).
    const int row0 = tid >> 1;            // 0..63
    const int kh0  = (tid & 1) * 8;
    const int row1 = row0 + 64;           // 64..127
    const float* Ap0 = A + (size_t)(m0 + row0) * DD + kh0;
    const float* Ap1 = A + (size_t)(m0 + row1) * DD + kh0;
    const float* Wp0 = W + (size_t)(n0 + row0) * DD + kh0;
    const float* Wp1 = W + (size_t)(n0 + row1) * DD + kh0;
    const int sb0 = row0 * GPAD + kh0;
    const int sb1 = row1 * GPAD + kh0;

    float acc[4][8][4];
#pragma unroll
    for (int i = 0; i < 4; i++)
#pragma unroll
        for (int j = 0; j < 8; j++)
#pragma unroll
            for (int c = 0; c < 4; c++) acc[i][j][c] = 0.f;

    // Prefetch registers: 2 half-rows x 2 float4, per array.
    float4 rA0a, rA0b, rA1a, rA1b, rB0a, rB0b, rB1a, rB1b;
    rA0a = *(const float4*)(Ap0);     rA0b = *(const float4*)(Ap0 + 4);
    rA1a = *(const float4*)(Ap1);     rA1b = *(const float4*)(Ap1 + 4);
    rB0a = *(const float4*)(Wp0);     rB0b = *(const float4*)(Wp0 + 4);
    rB1a = *(const float4*)(Wp1);     rB1b = *(const float4*)(Wp1 + 4);

    // Scalar pair-interleaved half-row store: pos 0..7 = k0,k4,k1,k5,k2,k6,k3,k7.
    auto sts_half = [&](uint32_t* S, int sb, float4 lo, float4 hi) {
        S[sb + 0] = f2tf32(lo.x); S[sb + 2] = f2tf32(lo.y);
        S[sb + 4] = f2tf32(lo.z); S[sb + 6] = f2tf32(lo.w);
        S[sb + 1] = f2tf32(hi.x); S[sb + 3] = f2tf32(hi.y);
        S[sb + 5] = f2tf32(hi.z); S[sb + 7] = f2tf32(hi.w);
    };

    auto sts_tile = [&](uint32_t* SA, uint32_t* SB) {
        sts_half(SA, sb0, rA0a, rA0b);
        sts_half(SA, sb1, rA1a, rA1b);
        sts_half(SB, sb0, rB0a, rB0b);
        sts_half(SB, sb1, rB1a, rB1b);
    };

    sts_tile(As[0], Bs[0]);
    __syncthreads();

    int cur = 0;
    const int NTILES = DD / 16;
    for (int it = 0; it < NTILES; ++it) {
        if (it + 1 < NTILES) {
            const int ko = (it + 1) * 16;
            rA0a = *(const float4*)(Ap0 + ko);  rA0b = *(const float4*)(Ap0 + ko + 4);
            rA1a = *(const float4*)(Ap1 + ko);  rA1b = *(const float4*)(Ap1 + ko + 4);
            rB0a = *(const float4*)(Wp0 + ko);  rB0b = *(const float4*)(Wp0 + ko + 4);
            rB1a = *(const float4*)(Wp1 + ko);  rB1b = *(const float4*)(Wp1 + ko + 4);
        }

        const uint32_t* SA = As[cur];
        const uint32_t* SB = Bs[cur];
#pragma unroll
        for (int s = 0; s < 2; s++) {
            uint32_t a[4][4];
#pragma unroll
            for (int mi = 0; mi < 4; mi++) {
                const int r0 = wm * 64 + mi * 16 + g;
                uint2 p0 = *(const uint2*)&SA[r0 * GPAD + s * 8 + 2 * t];
                uint2 p1 = *(const uint2*)&SA[(r0 + 8) * GPAD + s * 8 + 2 * t];
                a[mi][0] = p0.x; a[mi][1] = p1.x; a[mi][2] = p0.y; a[mi][3] = p1.y;
            }
            uint32_t b[8][2];
#pragma unroll
            for (int nj = 0; nj < 8; nj++) {
                uint2 q = *(const uint2*)&SB[(wn * 64 + nj * 8 + g) * GPAD + s * 8 + 2 * t];
                b[nj][0] = q.x; b[nj][1] = q.y;
            }
#pragma unroll
            for (int mi = 0; mi < 4; mi++)
#pragma unroll
                for (int nj = 0; nj < 8; nj++)
                    mma_tf32(acc[mi][nj][0], acc[mi][nj][1], acc[mi][nj][2], acc[mi][nj][3],
                             a[mi][0], a[mi][1], a[mi][2], a[mi][3],
                             b[nj][0], b[nj][1]);
        }

        if (it + 1 < NTILES) {
            sts_tile(As[cur ^ 1], Bs[cur ^ 1]);
            __syncthreads();
            cur ^= 1;
        }
    }

#pragma unroll
    for (int mi = 0; mi < 4; mi++) {
#pragma unroll
        for (int nj = 0; nj < 8; nj++) {
            const int n = n0 + wn * 64 + nj * 8 + 2 * t;
            const float bn0 = __ldg(&bias[n]);
            const float bn1 = __ldg(&bias[n + 1]);
#pragma unroll
            for (int rr = 0; rr < 2; rr++) {
                const int m = m0 + wm * 64 + mi * 16 + g + rr * 8;
                const float v0 = acc[mi][nj][rr * 2 + 0] + bn0;
                const float v1 = acc[mi][nj][rr * 2 + 1] + bn1;
                if (!QKV) {
                    *(float2*)&C[(size_t)m * DD + n] = make_float2(v0, v1);
                } else {
                    const int bb = m >> 10;
                    const int s  = m & (SS - 1);
                    const int h  = n >> 6;
                    const int dk = n & (DKK - 1);
                    float* dst = (z == 0) ? g_q : (z == 1) ? g_k : g_v;
                    *(float2*)&dst[(((size_t)(bb * HH + h)) * SS + s) * DKK + dk] =
                        make_float2(v0, v1);
                }
            }
        }
    }
}

// ---------------------------------------------------------------------------
// Mask bit-pack: one warp packs 32 ints -> 1 uint32 via ballot.
// ---------------------------------------------------------------------------
__global__ __launch_bounds__(256) void pack_mask(const int* __restrict__ mask) {
    const int gid = blockIdx.x * 256 + threadIdx.x;
    const int v = mask[gid] != 0;
    const uint32_t bits = __ballot_sync(0xffffffffu, v);
    if ((threadIdx.x & 31) == 0) g_mbits[gid >> 5] = bits;
}

// ---------------------------------------------------------------------------
// Tensor-core flash attention — R14-proven structure, ATP back to 72 (PV
// V-reads are conflict-free ONLY at ATP==72: banks 8t+8nj+ig cover all 32;
// ATP=74 made them 2-way -> R15 regression). NEW: Ps ALIASES Qs — Qs is dead
// after the aq-fragment extraction (pre-loop), Ps is first written two
// __syncthreads later. SMEM 73728 -> 55296 B => 3 -> 4 CTAs/SM (12 -> 16
// warps/SM), identical instruction stream. Grid (S/64, B*H), 128 thr.
// ---------------------------------------------------------------------------
#define ATP 72

__global__ __launch_bounds__(128) void attn_tc() {
    extern __shared__ uint32_t smu[];
    uint32_t* Qs = smu;              // [64 q][ATP] d-interleaved (prologue only)
    uint32_t* Ks = Qs + 64 * ATP;    // [64 kk][ATP] d-interleaved
    uint32_t* Vs = Ks + 64 * ATP;    // [64 kk][ATP] d-interleaved
    uint32_t* Ps = Qs;               // [64 q][ATP] kk-interleaved — ALIASES Qs

    const int tid  = threadIdx.x;
    const int lane = tid & 31;
    const int warp = tid >> 5;
    const int g = lane >> 2;
    const int t = lane & 3;
    const int bh = blockIdx.y;
    const int b = bh >> 4, h = bh & 15;
    const int q0 = blockIdx.x * 64;

    const float* qg = g_q + ((size_t)bh * SS + q0) * DKK;
    const float* kg = g_k + (size_t)bh * SS * DKK;
    const float* vg = g_v + (size_t)bh * SS * DKK;

#pragma unroll
    for (int u = 0; u < 8; u++) {
        const int off = tid + u * 128;
        float4 qv = *(const float4*)(qg + (size_t)off * 4);
        const int row = off >> 4;
        const int d0  = (off & 15) * 4;
        const int base = row * ATP + (d0 >> 3) * 8 + ((d0 & 7) ? 1 : 0);
        Qs[base + 0] = f2tf32(qv.x); Qs[base + 2] = f2tf32(qv.y);
        Qs[base + 4] = f2tf32(qv.z); Qs[base + 6] = f2tf32(qv.w);
    }
    __syncthreads();

    // Q fragments extracted once; Qs storage is dead afterwards (reused as Ps).
    uint32_t aq[8][4];
#pragma unroll
    for (int ks = 0; ks < 8; ks++) {
        uint2 p0 = *(const uint2*)&Qs[(warp * 16 + g) * ATP + ks * 8 + 2 * t];
        uint2 p1 = *(const uint2*)&Qs[(warp * 16 + g + 8) * ATP + ks * 8 + 2 * t];
        aq[ks][0] = p0.x; aq[ks][1] = p1.x; aq[ks][2] = p0.y; aq[ks][3] = p1.y;
    }

    float o[8][4];
#pragma unroll
    for (int nj = 0; nj < 8; nj++)
#pragma unroll
        for (int c = 0; c < 4; c++) o[nj][c] = 0.f;
    float m0 = -1e30f, m1 = -1e30f, l0 = 0.f, l1 = 0.f;

    const uint32_t* mrow = g_mbits + ((size_t)b * SS + (q0 + warp * 16 + g)) * (SS / 32);
    const int ig = 2 * (g & 3) + (g >> 2);

    for (int kt = 0; kt < 16; kt++) {
        __syncthreads();   // all warps past aq-extract (kt=0) / past PV (kt>0)
#pragma unroll
        for (int u = 0; u < 8; u++) {
            const int off = tid + u * 128;
            const int row = off >> 4;
            const int d0  = (off & 15) * 4;
            const int base = row * ATP + (d0 >> 3) * 8 + ((d0 & 7) ? 1 : 0);
            float4 kv = *(const float4*)(kg + (size_t)kt * 4096 + (size_t)off * 4);
            Ks[base + 0] = f2tf32(kv.x); Ks[base + 2] = f2tf32(kv.y);
            Ks[base + 4] = f2tf32(kv.z); Ks[base + 6] = f2tf32(kv.w);
            float4 vv = *(const float4*)(vg + (size_t)kt * 4096 + (size_t)off * 4);
            Vs[base + 0] = f2tf32(vv.x); Vs[base + 2] = f2tf32(vv.y);
            Vs[base + 4] = f2tf32(vv.z); Vs[base + 6] = f2tf32(vv.w);
        }
        __syncthreads();

        // S = Q K^T  (16 x 64 per warp)
        float s[8][4];
#pragma unroll
        for (int nj = 0; nj < 8; nj++)
#pragma unroll
            for (int c = 0; c < 4; c++) s[nj][c] = 0.f;
#pragma unroll
        for (int nj = 0; nj < 8; nj++)
#pragma unroll
            for (int ks = 0; ks < 8; ks++) {
                uint2 kb = *(const uint2*)&Ks[(nj * 8 + g) * ATP + ks * 8 + 2 * t];
                mma_tf32(s[nj][0], s[nj][1], s[nj][2], s[nj][3],
                         aq[ks][0], aq[ks][1], aq[ks][2], aq[ks][3], kb.x, kb.y);
            }

        // Mask + scale (bit-packed).
        const uint32_t w0lo = mrow[kt * 2];
        const uint32_t w0hi = mrow[kt * 2 + 1];
        const uint32_t w1lo = mrow[8 * (SS / 32) + kt * 2];
        const uint32_t w1hi = mrow[8 * (SS / 32) + kt * 2 + 1];
#pragma unroll
        for (int nj = 0; nj < 8; nj++) {
            const uint32_t wr0 = (nj < 4) ? w0lo : w0hi;
            const uint32_t wr1 = (nj < 4) ? w1lo : w1hi;
            const int sh = (nj & 3) * 8 + 2 * t;
            s[nj][0] = ((wr0 >> sh) & 1u)       ? s[nj][0] * 0.125f : -1e9f;
            s[nj][1] = ((wr0 >> (sh + 1)) & 1u) ? s[nj][1] * 0.125f : -1e9f;
            s[nj][2] = ((wr1 >> sh) & 1u)       ? s[nj][2] * 0.125f : -1e9f;
            s[nj][3] = ((wr1 >> (sh + 1)) & 1u) ? s[nj][3] * 0.125f : -1e9f;
        }

        // Online softmax.
        float mx0 = -1e30f, mx1 = -1e30f;
#pragma unroll
        for (int nj = 0; nj < 8; nj++) {
            mx0 = fmaxf(mx0, fmaxf(s[nj][0], s[nj][1]));
            mx1 = fmaxf(mx1, fmaxf(s[nj][2], s[nj][3]));
        }
        mx0 = fmaxf(mx0, __shfl_xor_sync(0xffffffffu, mx0, 1));
        mx0 = fmaxf(mx0, __shfl_xor_sync(0xffffffffu, mx0, 2));
        mx1 = fmaxf(mx1, __shfl_xor_sync(0xffffffffu, mx1, 1));
        mx1 = fmaxf(mx1, __shfl_xor_sync(0xffffffffu, mx1, 2));
        const float mn0 = fmaxf(m0, mx0), mn1 = fmaxf(m1, mx1);
        const float cr0 = __expf(m0 - mn0), cr1 = __expf(m1 - mn1);
        m0 = mn0; m1 = mn1;

        const int pa = 2 * ((2 * t) & 3) + ((2 * t) >> 2);
        const int pb = 2 * ((2 * t + 1) & 3) + ((2 * t + 1) >> 2);
        float rs0 = 0.f, rs1 = 0.f;
#pragma unroll
        for (int nj = 0; nj < 8; nj++) {
            const float p0 = __uint_as_float(f2tf32(__expf(s[nj][0] - m0)));
            const float p1 = __uint_as_float(f2tf32(__expf(s[nj][1] - m0)));
            const float p2 = __uint_as_float(f2tf32(__expf(s[nj][2] - m1)));
            const float p3 = __uint_as_float(f2tf32(__expf(s[nj][3] - m1)));
            rs0 += p0 + p1;
            rs1 += p2 + p3;
            const int pb0 = (warp * 16 + g) * ATP + nj * 8;
            const int pb1 = (warp * 16 + g + 8) * ATP + nj * 8;
            Ps[pb0 + pa] = __float_as_uint(p0);
            Ps[pb0 + pb] = __float_as_uint(p1);
            Ps[pb1 + pa] = __float_as_uint(p2);
            Ps[pb1 + pb] = __float_as_uint(p3);
        }
        rs0 += __shfl_xor_sync(0xffffffffu, rs0, 1);
        rs0 += __shfl_xor_sync(0xffffffffu, rs0, 2);
        rs1 += __shfl_xor_sync(0xffffffffu, rs1, 1);
        rs1 += __shfl_xor_sync(0xffffffffu, rs1, 2);
        l0 = l0 * cr0 + rs0;
        l1 = l1 * cr1 + rs1;
#pragma unroll
        for (int nj = 0; nj < 8; nj++) {
            o[nj][0] *= cr0; o[nj][1] *= cr0;
            o[nj][2] *= cr1; o[nj][3] *= cr1;
        }
        __syncwarp();

        // O += P V
#pragma unroll
        for (int ks = 0; ks < 8; ks++) {
            uint2 p0 = *(const uint2*)&Ps[(warp * 16 + g) * ATP + ks * 8 + 2 * t];
            uint2 p1 = *(const uint2*)&Ps[(warp * 16 + g + 8) * ATP + ks * 8 + 2 * t];
#pragma unroll
            for (int nj = 0; nj < 8; nj++) {
                const uint32_t b0 = Vs[(ks * 8 + t) * ATP + nj * 8 + ig];
                const uint32_t b1 = Vs[(ks * 8 + t + 4) * ATP + nj * 8 + ig];
                mma_tf32(o[nj][0], o[nj][1], o[nj][2], o[nj][3],
                         p0.x, p1.x, p0.y, p1.y, b0, b1);
            }
        }
        __syncwarp();
    }

    // Epilogue.
    const float i0 = 1.f / l0, i1 = 1.f / l1;
    const size_t r0 = ((size_t)(b * SS + q0 + warp * 16 + g)) * DD + h * 64;
    const size_t r1 = r0 + (size_t)8 * DD;
#pragma unroll
    for (int nj = 0; nj < 8; nj++) {
        *(float2*)&g_x[r0 + nj * 8 + 2 * t] = make_float2(o[nj][0] * i0, o[nj][1] * i0);
        *(float2*)&g_x[r1 + nj * 8 + 2 * t] = make_float2(o[nj][2] * i1, o[nj][3] * i1);
    }
}

// ---------------------------------------------------------------------------
extern "C" void kernel_launch(void* const* d_in, const int* in_sizes, int n_in,
                              void* d_out, int out_size) {
    const float* query = (const float*)d_in[0];
    const float* key   = (const float*)d_in[1];
    const float* value = (const float*)d_in[2];
    const int*   mask  = (const int*)d_in[3];
    const float* wq = (const float*)d_in[4];
    const float* bq = (const float*)d_in[5];
    const float* wk = (const float*)d_in[6];
    const float* bk = (const float*)d_in[7];
    const float* wv = (const float*)d_in[8];
    const float* bv = (const float*)d_in[9];
    const float* wo = (const float*)d_in[10];
    const float* bo = (const float*)d_in[11];
    float* out = (float*)d_out;

    static int smem_ok = 0;
    const int attn_smem = 3 * 64 * ATP * (int)sizeof(uint32_t);  // 55296 B (Ps aliases Qs)
    if (!smem_ok) {
        cudaFuncSetAttribute(attn_tc, cudaFuncAttributeMaxDynamicSharedMemorySize,
                             attn_smem);
        smem_ok = 1;
    }

    pack_mask<<<(BB * SS * SS) / 256, 256>>>(mask);

    dim3 gq(DD / 128, (BB * SS) / 128, 3);  // fused QKV
    gemm_tc<1><<<gq, 128>>>(query, key, value, wq, wk, wv, bq, bk, bv, nullptr);

    attn_tc<<<dim3(SS / 64, BB * HH), 128, attn_smem>>>();

    dim3 go(DD / 128, (BB * SS) / 128, 1);
    gemm_tc<0><<<go, 128>>>(nullptr, nullptr, nullptr, wo, nullptr, nullptr,
                            bo, nullptr, nullptr, out);
}

// round 17
// speedup vs baseline: 1.0530x; 1.0186x over previous
#include <cuda_runtime.h>
#include <math.h>
#include <stdint.h>

#define BB 4
#define SS 1024
#define DD 1024
#define HH 16
#define DKK 64

// Scratch (no allocations allowed).
// g_q/g_k/g_v now hold TF32 BITS in attention's pair-interleaved order:
// within each 8-group, element k sits at position p(k) = 2k (k<4) / 2k-7 (k>=4).
__device__ uint32_t g_q[BB * HH * SS * DKK];
__device__ uint32_t g_k[BB * HH * SS * DKK];
__device__ uint32_t g_v[BB * HH * SS * DKK];
__device__ float g_x[BB * SS * DD];
__device__ uint32_t g_mbits[BB * SS * (SS / 32)];

__device__ __forceinline__ uint32_t f2tf32(float x) {
    uint32_t r;
    asm("cvt.rna.tf32.f32 %0, %1;" : "=r"(r) : "f"(x));
    return r;
}

__device__ __forceinline__ void mma_tf32(float& c0, float& c1, float& c2, float& c3,
                                         uint32_t a0, uint32_t a1, uint32_t a2, uint32_t a3,
                                         uint32_t b0, uint32_t b1) {
    asm volatile(
        "mma.sync.aligned.m16n8k8.row.col.f32.tf32.tf32.f32 "
        "{%0,%1,%2,%3}, {%4,%5,%6,%7}, {%8,%9}, {%0,%1,%2,%3};"
        : "+f"(c0), "+f"(c1), "+f"(c2), "+f"(c3)
        : "r"(a0), "r"(a1), "r"(a2), "r"(a3), "r"(b0), "r"(b1));
}

// ---------------------------------------------------------------------------
// NT tensor-core GEMM (tf32) — R14-proven mainloop (GPAD=18). Epilogue for
// QKV now writes TF32 BITS pre-interleaved for attention (two STG.32 at
// positions pa, pa+2 within the dk 8-group; values bit-identical to the old
// fp32-store + attention-side cvt). Out-proj path unchanged (fp32, A=g_x).
// ---------------------------------------------------------------------------
#define GPAD 18

template <int QKV>
__global__ __launch_bounds__(128) void gemm_tc(const float* __restrict__ A0,
                                               const float* __restrict__ A1,
                                               const float* __restrict__ A2,
                                               const float* __restrict__ W0,
                                               const float* __restrict__ W1,
                                               const float* __restrict__ W2,
                                               const float* __restrict__ B0,
                                               const float* __restrict__ B1,
                                               const float* __restrict__ B2,
                                               float* __restrict__ C) {
    __shared__ uint32_t As[2][128 * GPAD];
    __shared__ uint32_t Bs[2][128 * GPAD];

    const int tid  = threadIdx.x;
    const int lane = tid & 31;
    const int warp = tid >> 5;       // 0..3
    const int wm   = warp >> 1;      // 0..1
    const int wn   = warp & 1;       // 0..1
    const int g    = lane >> 2;      // 0..7
    const int t    = lane & 3;       // 0..3
    const int m0 = blockIdx.y * 128;
    const int n0 = blockIdx.x * 128;
    const int z  = QKV ? blockIdx.z : 0;

    const float* A = QKV ? (z == 0 ? A0 : z == 1 ? A1 : A2) : g_x;  // device-side bind
    const float* W = QKV ? (z == 0 ? W0 : z == 1 ? W1 : W2) : W0;
    const float* bias = QKV ? (z == 0 ? B0 : z == 1 ? B1 : B2) : B0;

    // Staging: 2 half-rows per array per thread (256 half-rows / 128 thr).
    const int row0 = tid >> 1;            // 0..63
    const int kh0  = (tid & 1) * 8;
    const int row1 = row0 + 64;           // 64..127
    const float* Ap0 = A + (size_t)(m0 + row0) * DD + kh0;
    const float* Ap1 = A + (size_t)(m0 + row1) * DD + kh0;
    const float* Wp0 = W + (size_t)(n0 + row0) * DD + kh0;
    const float* Wp1 = W + (size_t)(n0 + row1) * DD + kh0;
    const int sb0 = row0 * GPAD + kh0;
    const int sb1 = row1 * GPAD + kh0;

    float acc[4][8][4];
#pragma unroll
    for (int i = 0; i < 4; i++)
#pragma unroll
        for (int j = 0; j < 8; j++)
#pragma unroll
            for (int c = 0; c < 4; c++) acc[i][j][c] = 0.f;

    // Prefetch registers: 2 half-rows x 2 float4, per array.
    float4 rA0a, rA0b, rA1a, rA1b, rB0a, rB0b, rB1a, rB1b;
    rA0a = *(const float4*)(Ap0);     rA0b = *(const float4*)(Ap0 + 4);
    rA1a = *(const float4*)(Ap1);     rA1b = *(const float4*)(Ap1 + 4);
    rB0a = *(const float4*)(Wp0);     rB0b = *(const float4*)(Wp0 + 4);
    rB1a = *(const float4*)(Wp1);     rB1b = *(const float4*)(Wp1 + 4);

    // Scalar pair-interleaved half-row store: pos 0..7 = k0,k4,k1,k5,k2,k6,k3,k7.
    auto sts_half = [&](uint32_t* S, int sb, float4 lo, float4 hi) {
        S[sb + 0] = f2tf32(lo.x); S[sb + 2] = f2tf32(lo.y);
        S[sb + 4] = f2tf32(lo.z); S[sb + 6] = f2tf32(lo.w);
        S[sb + 1] = f2tf32(hi.x); S[sb + 3] = f2tf32(hi.y);
        S[sb + 5] = f2tf32(hi.z); S[sb + 7] = f2tf32(hi.w);
    };

    auto sts_tile = [&](uint32_t* SA, uint32_t* SB) {
        sts_half(SA, sb0, rA0a, rA0b);
        sts_half(SA, sb1, rA1a, rA1b);
        sts_half(SB, sb0, rB0a, rB0b);
        sts_half(SB, sb1, rB1a, rB1b);
    };

    sts_tile(As[0], Bs[0]);
    __syncthreads();

    int cur = 0;
    const int NTILES = DD / 16;
    for (int it = 0; it < NTILES; ++it) {
        if (it + 1 < NTILES) {
            const int ko = (it + 1) * 16;
            rA0a = *(const float4*)(Ap0 + ko);  rA0b = *(const float4*)(Ap0 + ko + 4);
            rA1a = *(const float4*)(Ap1 + ko);  rA1b = *(const float4*)(Ap1 + ko + 4);
            rB0a = *(const float4*)(Wp0 + ko);  rB0b = *(const float4*)(Wp0 + ko + 4);
            rB1a = *(const float4*)(Wp1 + ko);  rB1b = *(const float4*)(Wp1 + ko + 4);
        }

        const uint32_t* SA = As[cur];
        const uint32_t* SB = Bs[cur];
#pragma unroll
        for (int s = 0; s < 2; s++) {
            uint32_t a[4][4];
#pragma unroll
            for (int mi = 0; mi < 4; mi++) {
                const int r0 = wm * 64 + mi * 16 + g;
                uint2 p0 = *(const uint2*)&SA[r0 * GPAD + s * 8 + 2 * t];
                uint2 p1 = *(const uint2*)&SA[(r0 + 8) * GPAD + s * 8 + 2 * t];
                a[mi][0] = p0.x; a[mi][1] = p1.x; a[mi][2] = p0.y; a[mi][3] = p1.y;
            }
            uint32_t b[8][2];
#pragma unroll
            for (int nj = 0; nj < 8; nj++) {
                uint2 q = *(const uint2*)&SB[(wn * 64 + nj * 8 + g) * GPAD + s * 8 + 2 * t];
                b[nj][0] = q.x; b[nj][1] = q.y;
            }
#pragma unroll
            for (int mi = 0; mi < 4; mi++)
#pragma unroll
                for (int nj = 0; nj < 8; nj++)
                    mma_tf32(acc[mi][nj][0], acc[mi][nj][1], acc[mi][nj][2], acc[mi][nj][3],
                             a[mi][0], a[mi][1], a[mi][2], a[mi][3],
                             b[nj][0], b[nj][1]);
        }

        if (it + 1 < NTILES) {
            sts_tile(As[cur ^ 1], Bs[cur ^ 1]);
            __syncthreads();
            cur ^= 1;
        }
    }

    // Interleaved position of k = 2t within its 8-group (pa), pair partner +2.
    const int pa = (t < 2) ? (4 * t) : (4 * t - 7);

#pragma unroll
    for (int mi = 0; mi < 4; mi++) {
#pragma unroll
        for (int nj = 0; nj < 8; nj++) {
            const int n = n0 + wn * 64 + nj * 8 + 2 * t;
            const float bn0 = __ldg(&bias[n]);
            const float bn1 = __ldg(&bias[n + 1]);
#pragma unroll
            for (int rr = 0; rr < 2; rr++) {
                const int m = m0 + wm * 64 + mi * 16 + g + rr * 8;
                const float v0 = acc[mi][nj][rr * 2 + 0] + bn0;
                const float v1 = acc[mi][nj][rr * 2 + 1] + bn1;
                if (!QKV) {
                    *(float2*)&C[(size_t)m * DD + n] = make_float2(v0, v1);
                } else {
                    const int bb = m >> 10;
                    const int s  = m & (SS - 1);
                    const int h  = n >> 6;
                    const int dk = n & (DKK - 1);
                    uint32_t* dst = (z == 0) ? g_q : (z == 1) ? g_k : g_v;
                    const size_t gb =
                        (((size_t)(bb * HH + h)) * SS + s) * DKK + (size_t)(dk & ~7);
                    dst[gb + pa]     = f2tf32(v0);
                    dst[gb + pa + 2] = f2tf32(v1);
                }
            }
        }
    }
}

// ---------------------------------------------------------------------------
// Mask bit-pack: one warp packs 32 ints -> 1 uint32 via ballot.
// ---------------------------------------------------------------------------
__global__ __launch_bounds__(256) void pack_mask(const int* __restrict__ mask) {
    const int gid = blockIdx.x * 256 + threadIdx.x;
    const int v = mask[gid] != 0;
    const uint32_t bits = __ballot_sync(0xffffffffu, v);
    if ((threadIdx.x & 31) == 0) g_mbits[gid >> 5] = bits;
}

// ---------------------------------------------------------------------------
// Tensor-core flash attention — R16-proven structure (ATP=72, Ps aliases Qs).
// Tile loaders are now PURE uint4 COPIES (g_q/g_k/g_v already hold tf32 bits
// in the interleaved SMEM order): 8 LDG.128 + 8 STS.128 per thread per tile,
// replacing 8 LDG + 64 cvt + 64 STS.32. STS.128 is conflict-free (phase
// banks 4l distinct) and 16B-aligned (72 words = 288 B = 18*16).
// ---------------------------------------------------------------------------
#define ATP 72

__global__ __launch_bounds__(128) void attn_tc() {
    extern __shared__ uint32_t smu[];
    uint32_t* Qs = smu;              // [64 q][ATP] (prologue only)
    uint32_t* Ks = Qs + 64 * ATP;    // [64 kk][ATP]
    uint32_t* Vs = Ks + 64 * ATP;    // [64 kk][ATP]
    uint32_t* Ps = Qs;               // [64 q][ATP] — ALIASES Qs (dead after aq)

    const int tid  = threadIdx.x;
    const int lane = tid & 31;
    const int warp = tid >> 5;
    const int g = lane >> 2;
    const int t = lane & 3;
    const int bh = blockIdx.y;
    const int b = bh >> 4, h = bh & 15;
    const int q0 = blockIdx.x * 64;

    const uint32_t* qg = g_q + ((size_t)bh * SS + q0) * DKK;
    const uint32_t* kg = g_k + (size_t)bh * SS * DKK;
    const uint32_t* vg = g_v + (size_t)bh * SS * DKK;

    // Q tile: pure vector copy (bits already tf32 + interleaved).
#pragma unroll
    for (int u = 0; u < 8; u++) {
        const int off = tid + u * 128;
        const int row = off >> 4;
        const int w   = (off & 15) * 4;
        *(uint4*)&Qs[row * ATP + w] = *(const uint4*)(qg + (size_t)off * 4);
    }
    __syncthreads();

    // Q fragments extracted once; Qs storage is dead afterwards (reused as Ps).
    uint32_t aq[8][4];
#pragma unroll
    for (int ks = 0; ks < 8; ks++) {
        uint2 p0 = *(const uint2*)&Qs[(warp * 16 + g) * ATP + ks * 8 + 2 * t];
        uint2 p1 = *(const uint2*)&Qs[(warp * 16 + g + 8) * ATP + ks * 8 + 2 * t];
        aq[ks][0] = p0.x; aq[ks][1] = p1.x; aq[ks][2] = p0.y; aq[ks][3] = p1.y;
    }

    float o[8][4];
#pragma unroll
    for (int nj = 0; nj < 8; nj++)
#pragma unroll
        for (int c = 0; c < 4; c++) o[nj][c] = 0.f;
    float m0 = -1e30f, m1 = -1e30f, l0 = 0.f, l1 = 0.f;

    const uint32_t* mrow = g_mbits + ((size_t)b * SS + (q0 + warp * 16 + g)) * (SS / 32);
    const int ig = 2 * (g & 3) + (g >> 2);

    for (int kt = 0; kt < 16; kt++) {
        __syncthreads();   // all warps past aq-extract (kt=0) / past PV (kt>0)
#pragma unroll
        for (int u = 0; u < 8; u++) {
            const int off = tid + u * 128;
            const int row = off >> 4;
            const int w   = (off & 15) * 4;
            *(uint4*)&Ks[row * ATP + w] =
                *(const uint4*)(kg + (size_t)kt * 4096 + (size_t)off * 4);
            *(uint4*)&Vs[row * ATP + w] =
                *(const uint4*)(vg + (size_t)kt * 4096 + (size_t)off * 4);
        }
        __syncthreads();

        // S = Q K^T  (16 x 64 per warp)
        float s[8][4];
#pragma unroll
        for (int nj = 0; nj < 8; nj++)
#pragma unroll
            for (int c = 0; c < 4; c++) s[nj][c] = 0.f;
#pragma unroll
        for (int nj = 0; nj < 8; nj++)
#pragma unroll
            for (int ks = 0; ks < 8; ks++) {
                uint2 kb = *(const uint2*)&Ks[(nj * 8 + g) * ATP + ks * 8 + 2 * t];
                mma_tf32(s[nj][0], s[nj][1], s[nj][2], s[nj][3],
                         aq[ks][0], aq[ks][1], aq[ks][2], aq[ks][3], kb.x, kb.y);
            }

        // Mask + scale (bit-packed).
        const uint32_t w0lo = mrow[kt * 2];
        const uint32_t w0hi = mrow[kt * 2 + 1];
        const uint32_t w1lo = mrow[8 * (SS / 32) + kt * 2];
        const uint32_t w1hi = mrow[8 * (SS / 32) + kt * 2 + 1];
#pragma unroll
        for (int nj = 0; nj < 8; nj++) {
            const uint32_t wr0 = (nj < 4) ? w0lo : w0hi;
            const uint32_t wr1 = (nj < 4) ? w1lo : w1hi;
            const int sh = (nj & 3) * 8 + 2 * t;
            s[nj][0] = ((wr0 >> sh) & 1u)       ? s[nj][0] * 0.125f : -1e9f;
            s[nj][1] = ((wr0 >> (sh + 1)) & 1u) ? s[nj][1] * 0.125f : -1e9f;
            s[nj][2] = ((wr1 >> sh) & 1u)       ? s[nj][2] * 0.125f : -1e9f;
            s[nj][3] = ((wr1 >> (sh + 1)) & 1u) ? s[nj][3] * 0.125f : -1e9f;
        }

        // Online softmax.
        float mx0 = -1e30f, mx1 = -1e30f;
#pragma unroll
        for (int nj = 0; nj < 8; nj++) {
            mx0 = fmaxf(mx0, fmaxf(s[nj][0], s[nj][1]));
            mx1 = fmaxf(mx1, fmaxf(s[nj][2], s[nj][3]));
        }
        mx0 = fmaxf(mx0, __shfl_xor_sync(0xffffffffu, mx0, 1));
        mx0 = fmaxf(mx0, __shfl_xor_sync(0xffffffffu, mx0, 2));
        mx1 = fmaxf(mx1, __shfl_xor_sync(0xffffffffu, mx1, 1));
        mx1 = fmaxf(mx1, __shfl_xor_sync(0xffffffffu, mx1, 2));
        const float mn0 = fmaxf(m0, mx0), mn1 = fmaxf(m1, mx1);
        const float cr0 = __expf(m0 - mn0), cr1 = __expf(m1 - mn1);
        m0 = mn0; m1 = mn1;

        const int pa = 2 * ((2 * t) & 3) + ((2 * t) >> 2);
        const int pb = 2 * ((2 * t + 1) & 3) + ((2 * t + 1) >> 2);
        float rs0 = 0.f, rs1 = 0.f;
#pragma unroll
        for (int nj = 0; nj < 8; nj++) {
            const float p0 = __uint_as_float(f2tf32(__expf(s[nj][0] - m0)));
            const float p1 = __uint_as_float(f2tf32(__expf(s[nj][1] - m0)));
            const float p2 = __uint_as_float(f2tf32(__expf(s[nj][2] - m1)));
            const float p3 = __uint_as_float(f2tf32(__expf(s[nj][3] - m1)));
            rs0 += p0 + p1;
            rs1 += p2 + p3;
            const int pb0 = (warp * 16 + g) * ATP + nj * 8;
            const int pb1 = (warp * 16 + g + 8) * ATP + nj * 8;
            Ps[pb0 + pa] = __float_as_uint(p0);
            Ps[pb0 + pb] = __float_as_uint(p1);
            Ps[pb1 + pa] = __float_as_uint(p2);
            Ps[pb1 + pb] = __float_as_uint(p3);
        }
        rs0 += __shfl_xor_sync(0xffffffffu, rs0, 1);
        rs0 += __shfl_xor_sync(0xffffffffu, rs0, 2);
        rs1 += __shfl_xor_sync(0xffffffffu, rs1, 1);
        rs1 += __shfl_xor_sync(0xffffffffu, rs1, 2);
        l0 = l0 * cr0 + rs0;
        l1 = l1 * cr1 + rs1;
#pragma unroll
        for (int nj = 0; nj < 8; nj++) {
            o[nj][0] *= cr0; o[nj][1] *= cr0;
            o[nj][2] *= cr1; o[nj][3] *= cr1;
        }
        __syncwarp();

        // O += P V
#pragma unroll
        for (int ks = 0; ks < 8; ks++) {
            uint2 p0 = *(const uint2*)&Ps[(warp * 16 + g) * ATP + ks * 8 + 2 * t];
            uint2 p1 = *(const uint2*)&Ps[(warp * 16 + g + 8) * ATP + ks * 8 + 2 * t];
#pragma unroll
            for (int nj = 0; nj < 8; nj++) {
                const uint32_t b0 = Vs[(ks * 8 + t) * ATP + nj * 8 + ig];
                const uint32_t b1 = Vs[(ks * 8 + t + 4) * ATP + nj * 8 + ig];
                mma_tf32(o[nj][0], o[nj][1], o[nj][2], o[nj][3],
                         p0.x, p1.x, p0.y, p1.y, b0, b1);
            }
        }
        __syncwarp();
    }

    // Epilogue.
    const float i0 = 1.f / l0, i1 = 1.f / l1;
    const size_t r0 = ((size_t)(b * SS + q0 + warp * 16 + g)) * DD + h * 64;
    const size_t r1 = r0 + (size_t)8 * DD;
#pragma unroll
    for (int nj = 0; nj < 8; nj++) {
        *(float2*)&g_x[r0 + nj * 8 + 2 * t] = make_float2(o[nj][0] * i0, o[nj][1] * i0);
        *(float2*)&g_x[r1 + nj * 8 + 2 * t] = make_float2(o[nj][2] * i1, o[nj][3] * i1);
    }
}

// ---------------------------------------------------------------------------
extern "C" void kernel_launch(void* const* d_in, const int* in_sizes, int n_in,
                              void* d_out, int out_size) {
    const float* query = (const float*)d_in[0];
    const float* key   = (const float*)d_in[1];
    const float* value = (const float*)d_in[2];
    const int*   mask  = (const int*)d_in[3];
    const float* wq = (const float*)d_in[4];
    const float* bq = (const float*)d_in[5];
    const float* wk = (const float*)d_in[6];
    const float* bk = (const float*)d_in[7];
    const float* wv = (const float*)d_in[8];
    const float* bv = (const float*)d_in[9];
    const float* wo = (const float*)d_in[10];
    const float* bo = (const float*)d_in[11];
    float* out = (float*)d_out;

    static int smem_ok = 0;
    const int attn_smem = 3 * 64 * ATP * (int)sizeof(uint32_t);  // 55296 B (Ps aliases Qs)
    if (!smem_ok) {
        cudaFuncSetAttribute(attn_tc, cudaFuncAttributeMaxDynamicSharedMemorySize,
                             attn_smem);
        smem_ok = 1;
    }

    pack_mask<<<(BB * SS * SS) / 256, 256>>>(mask);

    dim3 gq(DD / 128, (BB * SS) / 128, 3);  // fused QKV
    gemm_tc<1><<<gq, 128>>>(query, key, value, wq, wk, wv, bq, bk, bv, nullptr);

    attn_tc<<<dim3(SS / 64, BB * HH), 128, attn_smem>>>();

    dim3 go(DD / 128, (BB * SS) / 128, 1);
    gemm_tc<0><<<go, 128>>>(nullptr, nullptr, nullptr, wo, nullptr, nullptr,
                            bo, nullptr, nullptr, out);
}